// round 1
// baseline (speedup 1.0000x reference)
#include <cuda_runtime.h>
#include <cuda_bf16.h>

#define N_NODES 50000
#define D 128
#define R 8
#define E_PER 80000
#define NB 4
#define NF 4
#define V 1000
#define OUT 16
#define NKEYS (R * N_NODES)     // 400000
#define NEDGE (R * E_PER)       // 640000
#define KDIM 640                // 4*128 (M_b) + 128 (x)

#define SCAN_B 1024
#define SCAN_ITEMS 4
#define SCAN_TILE (SCAN_B * SCAN_ITEMS)
#define SCAN_NBLK ((NKEYS + SCAN_TILE - 1) / SCAN_TILE)   // 98

// ---------------- scratch (device globals; no allocation allowed) ----------
__device__ float g_A[(size_t)N_NODES * KDIM];   // [n][0..511]=M_b, [512..639]=x
__device__ int   g_counts[NKEYS];
__device__ int   g_offsets[NKEYS];
__device__ int   g_cursor[NKEYS];
__device__ int   g_partials[128];
__device__ int   g_csr_src[NEDGE];
__device__ float g_Wsum[D * D];
__device__ float g_biasH[D];

// ---------------- zero counts ----------------------------------------------
__global__ void k_zero() {
    int i = blockIdx.x * blockDim.x + threadIdx.x;
    if (i < NKEYS) g_counts[i] = 0;
}

// ---------------- x = sum_f emb[f, codes[f, nid[n]]] ------------------------
__global__ void k_gather_x(const int* __restrict__ fc, const int* __restrict__ nid,
                           const float* __restrict__ emb) {
    int w = (blockIdx.x * blockDim.x + threadIdx.x) >> 5;
    int lane = threadIdx.x & 31;
    if (w >= N_NODES) return;
    int node = nid[w];
    float4 acc = make_float4(0.f, 0.f, 0.f, 0.f);
#pragma unroll
    for (int f = 0; f < NF; f++) {
        int code = fc[f * N_NODES + node];
        const float4* src = (const float4*)(emb + ((size_t)f * V + code) * D);
        float4 v = src[lane];
        acc.x += v.x; acc.y += v.y; acc.z += v.z; acc.w += v.w;
    }
    ((float4*)(g_A + (size_t)w * KDIM + 512))[lane] = acc;
}

// ---------------- Wsum = sum_r W_self[r],  biasH = h_bias + sum_r b_rel -----
__global__ void k_prep(const float* __restrict__ W_self, const float* __restrict__ b_rel,
                       const float* __restrict__ h_bias) {
    int idx = blockIdx.x * blockDim.x + threadIdx.x;
    if (idx < D * D) {
        float s = 0.f;
#pragma unroll
        for (int r = 0; r < R; r++) s += W_self[r * D * D + idx];
        g_Wsum[idx] = s;
    }
    if (idx < D) {
        float s = h_bias[idx];
#pragma unroll
        for (int r = 0; r < R; r++) s += b_rel[r * D + idx];
        g_biasH[idx] = s;
    }
}

// ---------------- CSR build: count -> scan -> fill --------------------------
__global__ void k_count(const int* __restrict__ edst) {
    int i = blockIdx.x * blockDim.x + threadIdx.x;
    if (i >= NEDGE) return;
    int r = i / E_PER;
    int d = edst[i];
    atomicAdd(&g_counts[r * N_NODES + d], 1);
}

__global__ void k_scan1() {
    __shared__ int s[SCAN_B];
    int tid = threadIdx.x;
    int base = blockIdx.x * SCAN_TILE + tid * SCAN_ITEMS;
    int local[SCAN_ITEMS];
    int tsum = 0;
#pragma unroll
    for (int q = 0; q < SCAN_ITEMS; q++) {
        int idx = base + q;
        local[q] = (idx < NKEYS) ? g_counts[idx] : 0;
        tsum += local[q];
    }
    s[tid] = tsum;
    __syncthreads();
    for (int off = 1; off < SCAN_B; off <<= 1) {
        int v = 0;
        if (tid >= off) v = s[tid - off];
        __syncthreads();
        s[tid] += v;
        __syncthreads();
    }
    int excl = s[tid] - tsum;
    int run = excl;
#pragma unroll
    for (int q = 0; q < SCAN_ITEMS; q++) {
        int idx = base + q;
        if (idx < NKEYS) g_offsets[idx] = run;
        run += local[q];
    }
    if (tid == SCAN_B - 1) g_partials[blockIdx.x] = s[tid];
}

__global__ void k_scan2() {
    __shared__ int s[128];
    int tid = threadIdx.x;
    int v = (tid < SCAN_NBLK) ? g_partials[tid] : 0;
    s[tid] = v;
    __syncthreads();
    for (int off = 1; off < 128; off <<= 1) {
        int u = 0;
        if (tid >= off) u = s[tid - off];
        __syncthreads();
        s[tid] += u;
        __syncthreads();
    }
    if (tid < SCAN_NBLK) g_partials[tid] = s[tid] - v;  // exclusive
}

__global__ void k_scan3() {
    int add = g_partials[blockIdx.x];
    int base = blockIdx.x * SCAN_TILE;
#pragma unroll
    for (int q = 0; q < SCAN_ITEMS; q++) {
        int idx = base + threadIdx.x + q * SCAN_B;
        if (idx < NKEYS) {
            int v = g_offsets[idx] + add;
            g_offsets[idx] = v;
            g_cursor[idx] = v;
        }
    }
}

__global__ void k_fill(const int* __restrict__ esrc, const int* __restrict__ edst) {
    int i = blockIdx.x * blockDim.x + threadIdx.x;
    if (i >= NEDGE) return;
    int r = i / E_PER;
    int key = r * N_NODES + edst[i];
    int pos = atomicAdd(&g_cursor[key], 1);
    g_csr_src[pos] = esrc[i];
}

// ---------------- M_b accumulation (gather, warp per node) ------------------
__global__ void k_edge(const float* __restrict__ coeff) {
    int w = (blockIdx.x * blockDim.x + threadIdx.x) >> 5;
    int lane = threadIdx.x & 31;
    if (w >= N_NODES) return;

    float4 macc[NB];
#pragma unroll
    for (int b = 0; b < NB; b++) macc[b] = make_float4(0.f, 0.f, 0.f, 0.f);

    for (int r = 0; r < R; r++) {
        int key = r * N_NODES + w;
        int start = g_offsets[key];
        int cnt = g_counts[key];
        float4 ms = make_float4(0.f, 0.f, 0.f, 0.f);
        for (int e = 0; e < cnt; e++) {
            int s = g_csr_src[start + e];
            float4 v = ((const float4*)(g_A + (size_t)s * KDIM + 512))[lane];
            ms.x += v.x; ms.y += v.y; ms.z += v.z; ms.w += v.w;
        }
        float inv = 1.0f / fmaxf((float)cnt, 1.0f);
#pragma unroll
        for (int b = 0; b < NB; b++) {
            float c = coeff[r * NB + b] * inv;
            macc[b].x += c * ms.x;
            macc[b].y += c * ms.y;
            macc[b].z += c * ms.z;
            macc[b].w += c * ms.w;
        }
    }
#pragma unroll
    for (int b = 0; b < NB; b++)
        ((float4*)(g_A + (size_t)w * KDIM + b * D))[lane] = macc[b];
}

// ---------------- h = relu(A @ [basis;Wsum] + biasH) ------------------------
// BM=64 nodes, BN=128 cols, BK=32, 128 threads, 8x8 register tile per thread.
__global__ void __launch_bounds__(128) k_gemm(const float* __restrict__ basis,
                                              float* __restrict__ out) {
    __shared__ float As[32][64];   // [k][node] (transposed on store)
    __shared__ float Bs[32][128];  // [k][col]

    int tid = threadIdx.x;
    int tm = tid >> 4;   // 0..7
    int tn = tid & 15;   // 0..15
    int n0 = blockIdx.x * 64;

    float acc[8][8];
#pragma unroll
    for (int i = 0; i < 8; i++)
#pragma unroll
        for (int j = 0; j < 8; j++) acc[i][j] = 0.f;

    for (int kt = 0; kt < KDIM; kt += 32) {
        // A tile: 64 rows x 32 K  (512 float4 loads, 4 per thread)
#pragma unroll
        for (int q = 0; q < 4; q++) {
            int f = tid + q * 128;       // 0..511
            int row = f >> 3;
            int c4 = f & 7;
            float4 v = make_float4(0.f, 0.f, 0.f, 0.f);
            int gn = n0 + row;
            if (gn < N_NODES)
                v = *(const float4*)(g_A + (size_t)gn * KDIM + kt + c4 * 4);
            As[c4 * 4 + 0][row] = v.x;
            As[c4 * 4 + 1][row] = v.y;
            As[c4 * 4 + 2][row] = v.z;
            As[c4 * 4 + 3][row] = v.w;
        }
        // B tile: rows 0..511 come straight from basis (vstack(basis) == basis),
        // rows 512..639 from precomputed Wsum.
        const float* Bsrc = (kt < 512) ? (basis + (size_t)kt * D)
                                       : (g_Wsum + (size_t)(kt - 512) * D);
#pragma unroll
        for (int q = 0; q < 8; q++) {
            int f = tid + q * 128;       // 0..1023
            int row = f >> 5;
            int c4 = f & 31;
            float4 v = *(const float4*)(Bsrc + row * D + c4 * 4);
            *(float4*)&Bs[row][c4 * 4] = v;
        }
        __syncthreads();

#pragma unroll
        for (int k = 0; k < 32; k++) {
            float a[8], b[8];
#pragma unroll
            for (int ii = 0; ii < 4; ii++) {
                a[ii]     = As[k][tm * 4 + ii];
                a[4 + ii] = As[k][32 + tm * 4 + ii];
            }
#pragma unroll
            for (int jj = 0; jj < 4; jj++) {
                b[jj]     = Bs[k][tn * 4 + jj];
                b[4 + jj] = Bs[k][64 + tn * 4 + jj];
            }
#pragma unroll
            for (int i = 0; i < 8; i++)
#pragma unroll
                for (int j = 0; j < 8; j++) acc[i][j] += a[i] * b[j];
        }
        __syncthreads();
    }

    float* hout = out + (size_t)N_NODES * OUT;
#pragma unroll
    for (int i = 0; i < 8; i++) {
        int row = (i < 4) ? (tm * 4 + i) : (32 + tm * 4 + (i - 4));
        int gn = n0 + row;
        if (gn >= N_NODES) continue;
#pragma unroll
        for (int j = 0; j < 8; j++) {
            int col = (j < 4) ? (tn * 4 + j) : (64 + tn * 4 + (j - 4));
            float v = acc[i][j] + g_biasH[col];
            v = fmaxf(v, 0.f);
            hout[(size_t)gn * D + col] = v;
        }
    }
}

// ---------------- logits = h @ W_cls + b_cls --------------------------------
__global__ void k_logits(const float* __restrict__ W_cls, const float* __restrict__ b_cls,
                         float* __restrict__ out) {
    __shared__ float Wc[D * OUT];
    for (int i = threadIdx.x; i < D * OUT; i += blockDim.x) Wc[i] = W_cls[i];
    __syncthreads();
    int idx = blockIdx.x * blockDim.x + threadIdx.x;
    if (idx >= N_NODES * OUT) return;
    int n = idx >> 4;
    int o = idx & 15;
    const float* h = out + (size_t)N_NODES * OUT + (size_t)n * D;
    float s = b_cls[o];
#pragma unroll 8
    for (int d = 0; d < D; d++) s += h[d] * Wc[d * OUT + o];
    out[idx] = s;
}

// ---------------- launch ----------------------------------------------------
extern "C" void kernel_launch(void* const* d_in, const int* in_sizes, int n_in,
                              void* d_out, int out_size) {
    const int*   feat_codes = (const int*)d_in[0];
    const int*   nid        = (const int*)d_in[1];
    const int*   esrc       = (const int*)d_in[2];
    const int*   edst       = (const int*)d_in[3];
    const float* emb        = (const float*)d_in[4];
    const float* basis      = (const float*)d_in[5];
    const float* coeff      = (const float*)d_in[6];
    const float* W_self     = (const float*)d_in[7];
    const float* b_rel      = (const float*)d_in[8];
    const float* h_bias     = (const float*)d_in[9];
    const float* W_cls      = (const float*)d_in[10];
    const float* b_cls      = (const float*)d_in[11];
    float* out = (float*)d_out;

    k_zero<<<(NKEYS + 1023) / 1024, 1024>>>();
    k_gather_x<<<(N_NODES + 7) / 8, 256>>>(feat_codes, nid, emb);
    k_prep<<<(D * D + 255) / 256, 256>>>(W_self, b_rel, h_bias);
    k_count<<<(NEDGE + 255) / 256, 256>>>(edst);
    k_scan1<<<SCAN_NBLK, SCAN_B>>>();
    k_scan2<<<1, 128>>>();
    k_scan3<<<SCAN_NBLK, SCAN_B>>>();
    k_fill<<<(NEDGE + 255) / 256, 256>>>(esrc, edst);
    k_edge<<<(N_NODES + 7) / 8, 256>>>(coeff);
    k_gemm<<<(N_NODES + 63) / 64, 128>>>(basis, out);
    k_logits<<<(N_NODES * OUT + 255) / 256, 256>>>(W_cls, b_cls, out);
}

// round 3
// speedup vs baseline: 1.7847x; 1.7847x over previous
#include <cuda_runtime.h>
#include <cuda_bf16.h>
#include <cstdint>

#define N_NODES 50000
#define N_PAD   50048            // 391 * 128
#define D 128
#define R 8
#define E_PER 80000
#define NB 4
#define NF 4
#define V 1000
#define OUT 16
#define NKEYS (R * N_NODES)      // 400000
#define NEDGE (R * E_PER)        // 640000
#define KDIM 640                 // 4*128 (M_b) + 128 (x)

#define SCAN_B 1024
#define SCAN_ITEMS 4
#define SCAN_TILE (SCAN_B * SCAN_ITEMS)
#define SCAN_NBLK ((NKEYS + SCAN_TILE - 1) / SCAN_TILE)   // 98

// ---------------- scratch (device globals; no allocation allowed) ----------
__device__ float g_x[(size_t)N_NODES * D];                     // fp32 features (exact)
__device__ __align__(16) __nv_bfloat16 g_Ahi[(size_t)N_PAD * KDIM];
__device__ __align__(16) __nv_bfloat16 g_Alo[(size_t)N_PAD * KDIM];
__device__ __align__(16) __nv_bfloat16 g_Bhi[D * KDIM];        // B^T [n][k]
__device__ __align__(16) __nv_bfloat16 g_Blo[D * KDIM];
__device__ int   g_counts[NKEYS];
__device__ int   g_offsets[NKEYS];
__device__ int   g_cursor[NKEYS];
__device__ int   g_partials[128];
__device__ int   g_csr_src[NEDGE];
__device__ float g_biasH[D];

// ======================= PTX helpers (sm_80+ features only) =================
__device__ __forceinline__ uint32_t smem_u32(const void* p) {
    uint32_t a;
    asm("{ .reg .u64 t; cvta.to.shared.u64 t, %1; cvt.u32.u64 %0, t; }" : "=r"(a) : "l"(p));
    return a;
}
#define CP_ASYNC16(saddr, gaddr) \
    asm volatile("cp.async.cg.shared.global [%0], [%1], 16;" :: "r"(saddr), "l"(gaddr))
#define CP_COMMIT() asm volatile("cp.async.commit_group;" ::: "memory")
#define CP_WAIT(n)  asm volatile("cp.async.wait_group %0;" :: "n"(n) : "memory")

#define LDSM4(r, addr) \
    asm volatile("ldmatrix.sync.aligned.m8n8.x4.shared.b16 {%0,%1,%2,%3}, [%4];" \
        : "=r"((r)[0]), "=r"((r)[1]), "=r"((r)[2]), "=r"((r)[3]) : "r"(addr))

#define MMA16816(c, a, b) \
    asm volatile("mma.sync.aligned.m16n8k16.row.col.f32.bf16.bf16.f32 " \
        "{%0,%1,%2,%3}, {%4,%5,%6,%7}, {%8,%9}, {%0,%1,%2,%3};" \
        : "+f"((c)[0]), "+f"((c)[1]), "+f"((c)[2]), "+f"((c)[3]) \
        : "r"((a)[0]), "r"((a)[1]), "r"((a)[2]), "r"((a)[3]), \
          "r"((b)[0]), "r"((b)[1]))

// split-bf16: write float4 as 4 bf16 hi + 4 bf16 lo
__device__ __forceinline__ void split_store(float4 v, __nv_bfloat16* hi, __nv_bfloat16* lo) {
    __nv_bfloat16 h0 = __float2bfloat16_rn(v.x), h1 = __float2bfloat16_rn(v.y);
    __nv_bfloat16 h2 = __float2bfloat16_rn(v.z), h3 = __float2bfloat16_rn(v.w);
    float r0 = v.x - __bfloat162float(h0), r1 = v.y - __bfloat162float(h1);
    float r2 = v.z - __bfloat162float(h2), r3 = v.w - __bfloat162float(h3);
    __nv_bfloat162 a, b;
    a.x = h0; a.y = h1; b.x = h2; b.y = h3;
    uint2 uh; uh.x = *reinterpret_cast<unsigned*>(&a); uh.y = *reinterpret_cast<unsigned*>(&b);
    *reinterpret_cast<uint2*>(hi) = uh;
    __nv_bfloat162 c = __floats2bfloat162_rn(r0, r1), d = __floats2bfloat162_rn(r2, r3);
    uint2 ul; ul.x = *reinterpret_cast<unsigned*>(&c); ul.y = *reinterpret_cast<unsigned*>(&d);
    *reinterpret_cast<uint2*>(lo) = ul;
}

// ---------------- zero counts ----------------------------------------------
__global__ void k_zero() {
    int i = blockIdx.x * blockDim.x + threadIdx.x;
    if (i < NKEYS) g_counts[i] = 0;
}

// ---------------- x = sum_f emb[f, codes[f, nid[n]]]  (fp32 + split-bf16) ---
__global__ void k_gather_x(const int* __restrict__ fc, const int* __restrict__ nid,
                           const float* __restrict__ emb) {
    int w = (blockIdx.x * blockDim.x + threadIdx.x) >> 5;
    int lane = threadIdx.x & 31;
    if (w >= N_NODES) return;
    int node = nid[w];
    float4 acc = make_float4(0.f, 0.f, 0.f, 0.f);
#pragma unroll
    for (int f = 0; f < NF; f++) {
        int code = fc[f * N_NODES + node];
        const float4* src = (const float4*)(emb + ((size_t)f * V + code) * D);
        float4 v = src[lane];
        acc.x += v.x; acc.y += v.y; acc.z += v.z; acc.w += v.w;
    }
    ((float4*)(g_x + (size_t)w * D))[lane] = acc;
    size_t off = (size_t)w * KDIM + 512 + lane * 4;
    split_store(acc, g_Ahi + off, g_Alo + off);
}

// ---------------- B^T split + biasH -----------------------------------------
__global__ void k_prepB(const float* __restrict__ basis, const float* __restrict__ W_self,
                        const float* __restrict__ b_rel, const float* __restrict__ h_bias) {
    int idx = blockIdx.x * blockDim.x + threadIdx.x;
    if (idx < D) {
        float s = h_bias[idx];
#pragma unroll
        for (int r = 0; r < R; r++) s += b_rel[r * D + idx];
        g_biasH[idx] = s;
    }
    if (idx >= D * KDIM) return;
    int n = idx / KDIM;
    int k = idx % KDIM;
    float v;
    if (k < 512) {
        v = basis[(size_t)((k >> 7) * D + (k & 127)) * D + n];
    } else {
        v = 0.f;
#pragma unroll
        for (int r = 0; r < R; r++) v += W_self[(size_t)(r * D + (k - 512)) * D + n];
    }
    __nv_bfloat16 hi = __float2bfloat16_rn(v);
    g_Bhi[idx] = hi;
    g_Blo[idx] = __float2bfloat16_rn(v - __bfloat162float(hi));
}

// ---------------- CSR build: count -> scan -> fill --------------------------
__global__ void k_count(const int* __restrict__ edst) {
    int i = blockIdx.x * blockDim.x + threadIdx.x;
    if (i >= NEDGE) return;
    int r = i / E_PER;
    atomicAdd(&g_counts[r * N_NODES + edst[i]], 1);
}

__global__ void k_scan1() {
    __shared__ int s[SCAN_B];
    int tid = threadIdx.x;
    int base = blockIdx.x * SCAN_TILE + tid * SCAN_ITEMS;
    int local[SCAN_ITEMS];
    int tsum = 0;
#pragma unroll
    for (int q = 0; q < SCAN_ITEMS; q++) {
        int idx = base + q;
        local[q] = (idx < NKEYS) ? g_counts[idx] : 0;
        tsum += local[q];
    }
    s[tid] = tsum;
    __syncthreads();
    for (int off = 1; off < SCAN_B; off <<= 1) {
        int v = 0;
        if (tid >= off) v = s[tid - off];
        __syncthreads();
        s[tid] += v;
        __syncthreads();
    }
    int run = s[tid] - tsum;
#pragma unroll
    for (int q = 0; q < SCAN_ITEMS; q++) {
        int idx = base + q;
        if (idx < NKEYS) g_offsets[idx] = run;
        run += local[q];
    }
    if (tid == SCAN_B - 1) g_partials[blockIdx.x] = s[tid];
}

__global__ void k_scan2() {
    __shared__ int s[128];
    int tid = threadIdx.x;
    int v = (tid < SCAN_NBLK) ? g_partials[tid] : 0;
    s[tid] = v;
    __syncthreads();
    for (int off = 1; off < 128; off <<= 1) {
        int u = 0;
        if (tid >= off) u = s[tid - off];
        __syncthreads();
        s[tid] += u;
        __syncthreads();
    }
    if (tid < SCAN_NBLK) g_partials[tid] = s[tid] - v;
}

__global__ void k_scan3() {
    int add = g_partials[blockIdx.x];
    int base = blockIdx.x * SCAN_TILE;
#pragma unroll
    for (int q = 0; q < SCAN_ITEMS; q++) {
        int idx = base + threadIdx.x + q * SCAN_B;
        if (idx < NKEYS) {
            int v = g_offsets[idx] + add;
            g_offsets[idx] = v;
            g_cursor[idx] = v;
        }
    }
}

__global__ void k_fill(const int* __restrict__ esrc, const int* __restrict__ edst) {
    int i = blockIdx.x * blockDim.x + threadIdx.x;
    if (i >= NEDGE) return;
    int r = i / E_PER;
    int key = r * N_NODES + edst[i];
    int pos = atomicAdd(&g_cursor[key], 1);
    g_csr_src[pos] = esrc[i];
}

// ---------------- M_b accumulation (warp per node, fp32, split-bf16 out) ----
__global__ void k_edge(const float* __restrict__ coeff) {
    int w = (blockIdx.x * blockDim.x + threadIdx.x) >> 5;
    int lane = threadIdx.x & 31;
    if (w >= N_NODES) return;

    float4 macc[NB];
#pragma unroll
    for (int b = 0; b < NB; b++) macc[b] = make_float4(0.f, 0.f, 0.f, 0.f);

    for (int r = 0; r < R; r++) {
        int key = r * N_NODES + w;
        int start = g_offsets[key];
        int cnt = g_counts[key];
        float4 ms = make_float4(0.f, 0.f, 0.f, 0.f);
        for (int e = 0; e < cnt; e++) {
            int s = g_csr_src[start + e];
            float4 v = ((const float4*)(g_x + (size_t)s * D))[lane];
            ms.x += v.x; ms.y += v.y; ms.z += v.z; ms.w += v.w;
        }
        float inv = 1.0f / fmaxf((float)cnt, 1.0f);
#pragma unroll
        for (int b = 0; b < NB; b++) {
            float c = coeff[r * NB + b] * inv;
            macc[b].x += c * ms.x;
            macc[b].y += c * ms.y;
            macc[b].z += c * ms.z;
            macc[b].w += c * ms.w;
        }
    }
#pragma unroll
    for (int b = 0; b < NB; b++) {
        size_t off = (size_t)w * KDIM + b * D + lane * 4;
        split_store(macc[b], g_Ahi + off, g_Alo + off);
    }
}

// ---------------- mma.sync GEMM + fused bias/ReLU/logits epilogue ------------
// CTA: 128x128, 8 warps (4x2), warp tile 32x64, BK=32, double-buffered cp.async.
// D = Ah*Bh + Ah*Bl + Al*Bh  (split-bf16 emulated fp32, m16n8k16 HMMA)
#define BK 32
#define NSTAGE 20                 // KDIM / BK
#define SAS 80                    // smem row stride bytes (40 bf16, conflict-free)
#define TILE_B (128 * SAS)        // 10240 per matrix
#define OFF_AH 0
#define OFF_AL (1 * TILE_B)
#define OFF_BH (2 * TILE_B)
#define OFF_BL (3 * TILE_B)
#define STAGE_B (4 * TILE_B)      // 40960
#define OFF_WC   (2 * STAGE_B)    // 81920
#define OFF_BIAS (OFF_WC + 8192)
#define OFF_BCLS (OFF_BIAS + 512)
#define SM_TOTAL (OFF_BCLS + 128) // 90752  (staging 128x132 f32 = 67584 reuses tiles)
#define STG_STRIDE 132

__global__ void __launch_bounds__(256) k_gemm_mma(const float* __restrict__ W_cls,
                                                  const float* __restrict__ b_cls,
                                                  float* __restrict__ out) {
    extern __shared__ char smem[];
    uint32_t sb = smem_u32(smem);
    int tid = threadIdx.x;
    int lane = tid & 31, wid = tid >> 5;
    int wm = wid & 3, wn = wid >> 2;          // warp tile at (wm*32, wn*64)
    int n0 = blockIdx.x * 128;

    float* sWc   = (float*)(smem + OFF_WC);
    float* sBias = (float*)(smem + OFF_BIAS);
    float* sBcls = (float*)(smem + OFF_BCLS);
    for (int i = tid; i < D * OUT; i += 256) sWc[i] = W_cls[i];
    if (tid < D)   sBias[tid] = g_biasH[tid];
    if (tid < OUT) sBcls[tid] = b_cls[tid];

    float acc[2][8][4];
#pragma unroll
    for (int mt = 0; mt < 2; mt++)
#pragma unroll
        for (int nt = 0; nt < 8; nt++)
#pragma unroll
            for (int q = 0; q < 4; q++) acc[mt][nt][q] = 0.f;

    // -------- async tile loader --------
    auto load_stage = [&](int s) {
        uint32_t sm0 = sb + (s & 1) * STAGE_B;
        int k0 = s * BK;
#pragma unroll
        for (int q = 0; q < 2; q++) {
            int c = tid + q * 256;            // 0..511
            int row = c >> 2, kc = c & 3;
            uint32_t soff = row * SAS + kc * 16;
            size_t aoff = (size_t)(n0 + row) * KDIM + k0 + kc * 8;
            size_t boff = (size_t)row * KDIM + k0 + kc * 8;
            CP_ASYNC16(sm0 + OFF_AH + soff, g_Ahi + aoff);
            CP_ASYNC16(sm0 + OFF_AL + soff, g_Alo + aoff);
            CP_ASYNC16(sm0 + OFF_BH + soff, g_Bhi + boff);
            CP_ASYNC16(sm0 + OFF_BL + soff, g_Blo + boff);
        }
    };

    load_stage(0); CP_COMMIT();

    for (int s = 0; s < NSTAGE; s++) {
        if (s + 1 < NSTAGE) {
            load_stage(s + 1); CP_COMMIT();
            CP_WAIT(1);
        } else {
            CP_WAIT(0);
        }
        __syncthreads();

        uint32_t base = sb + (s & 1) * STAGE_B;
#pragma unroll
        for (int ks = 0; ks < 2; ks++) {
            uint32_t ah[2][4], al[2][4], bh[8][2], bl[8][2];
#pragma unroll
            for (int mt = 0; mt < 2; mt++) {
                uint32_t ro = (uint32_t)(wm * 32 + mt * 16 + (lane & 15)) * SAS
                              + ks * 32 + ((lane >> 4) << 4);
                LDSM4(ah[mt], base + OFF_AH + ro);
                LDSM4(al[mt], base + OFF_AL + ro);
            }
#pragma unroll
            for (int ntp = 0; ntp < 4; ntp++) {
                uint32_t ro = (uint32_t)(wn * 64 + ntp * 16 + ((lane >> 4) << 3) + (lane & 7)) * SAS
                              + ks * 32 + (((lane >> 3) & 1) << 4);
                uint32_t t[4];
                LDSM4(t, base + OFF_BH + ro);
                bh[2 * ntp][0] = t[0]; bh[2 * ntp][1] = t[1];
                bh[2 * ntp + 1][0] = t[2]; bh[2 * ntp + 1][1] = t[3];
                LDSM4(t, base + OFF_BL + ro);
                bl[2 * ntp][0] = t[0]; bl[2 * ntp][1] = t[1];
                bl[2 * ntp + 1][0] = t[2]; bl[2 * ntp + 1][1] = t[3];
            }
#pragma unroll
            for (int mt = 0; mt < 2; mt++)
#pragma unroll
                for (int nt = 0; nt < 8; nt++) {
                    MMA16816(acc[mt][nt], ah[mt], bh[nt]);
                    MMA16816(acc[mt][nt], ah[mt], bl[nt]);
                    MMA16816(acc[mt][nt], al[mt], bh[nt]);
                }
        }
        __syncthreads();
    }

    // -------- epilogue: bias + relu into staging smem --------
    float* stg = (float*)smem;                 // 128 x 132, reuses tile area
#pragma unroll
    for (int mt = 0; mt < 2; mt++) {
        int rl0 = wm * 32 + mt * 16 + (lane >> 2);
#pragma unroll
        for (int nt = 0; nt < 8; nt++) {
            int col0 = wn * 64 + nt * 8 + (lane & 3) * 2;
            stg[(rl0)     * STG_STRIDE + col0    ] = fmaxf(acc[mt][nt][0] + sBias[col0],     0.f);
            stg[(rl0)     * STG_STRIDE + col0 + 1] = fmaxf(acc[mt][nt][1] + sBias[col0 + 1], 0.f);
            stg[(rl0 + 8) * STG_STRIDE + col0    ] = fmaxf(acc[mt][nt][2] + sBias[col0],     0.f);
            stg[(rl0 + 8) * STG_STRIDE + col0 + 1] = fmaxf(acc[mt][nt][3] + sBias[col0 + 1], 0.f);
        }
    }
    __syncthreads();

    // -------- per-row: store h + compute logits --------
    if (tid < 128) {
        int node = n0 + tid;
        if (node < N_NODES) {
            float a[OUT];
#pragma unroll
            for (int o = 0; o < OUT; o++) a[o] = sBcls[o];
            const float4* row = (const float4*)(stg + tid * STG_STRIDE);
            float* hptr = out + (size_t)N_NODES * OUT + (size_t)node * D;
#pragma unroll
            for (int q = 0; q < 32; q++) {
                float4 v = row[q];
                const float* w0 = sWc + (q * 4) * OUT;
#pragma unroll
                for (int o = 0; o < OUT; o++)
                    a[o] += v.x * w0[o] + v.y * w0[OUT + o]
                          + v.z * w0[2 * OUT + o] + v.w * w0[3 * OUT + o];
                ((float4*)hptr)[q] = v;
            }
            float* lptr = out + (size_t)node * OUT;
#pragma unroll
            for (int q = 0; q < 4; q++) {
                float4 v;
                v.x = a[q * 4]; v.y = a[q * 4 + 1]; v.z = a[q * 4 + 2]; v.w = a[q * 4 + 3];
                ((float4*)lptr)[q] = v;
            }
        }
    }
}

// ---------------- launch ----------------------------------------------------
extern "C" void kernel_launch(void* const* d_in, const int* in_sizes, int n_in,
                              void* d_out, int out_size) {
    const int*   feat_codes = (const int*)d_in[0];
    const int*   nid        = (const int*)d_in[1];
    const int*   esrc       = (const int*)d_in[2];
    const int*   edst       = (const int*)d_in[3];
    const float* emb        = (const float*)d_in[4];
    const float* basis      = (const float*)d_in[5];
    const float* coeff      = (const float*)d_in[6];
    const float* W_self     = (const float*)d_in[7];
    const float* b_rel      = (const float*)d_in[8];
    const float* h_bias     = (const float*)d_in[9];
    const float* W_cls      = (const float*)d_in[10];
    const float* b_cls      = (const float*)d_in[11];
    float* out = (float*)d_out;

    static bool attr_set = false;
    if (!attr_set) {
        cudaFuncSetAttribute(k_gemm_mma, cudaFuncAttributeMaxDynamicSharedMemorySize, SM_TOTAL);
        attr_set = true;
    }

    k_zero<<<(NKEYS + 1023) / 1024, 1024>>>();
    k_gather_x<<<(N_NODES + 7) / 8, 256>>>(feat_codes, nid, emb);
    k_prepB<<<(D * KDIM + 255) / 256, 256>>>(basis, W_self, b_rel, h_bias);
    k_count<<<(NEDGE + 255) / 256, 256>>>(edst);
    k_scan1<<<SCAN_NBLK, SCAN_B>>>();
    k_scan2<<<1, 128>>>();
    k_scan3<<<SCAN_NBLK, SCAN_B>>>();
    k_fill<<<(NEDGE + 255) / 256, 256>>>(esrc, edst);
    k_edge<<<(N_NODES + 7) / 8, 256>>>(coeff);
    k_gemm_mma<<<N_PAD / 128, 256, SM_TOTAL>>>(W_cls, b_cls, out);
}